// round 4
// baseline (speedup 1.0000x reference)
#include <cuda_runtime.h>
#include <mma.h>

using namespace nvcuda;

// Problem dims (fixed)
#define DMODEL 1024
#define NH     16
#define DH     64
#define BATCH  4
#define SEQ    1024
#define BH     (BATCH*NH)          // 64
#define IT     2                   // i-values per CTA (fused attention)
#define JC     32                  // j chunk (fused attention)

// Scratch (static device globals; no runtime allocation allowed)
__device__ float g_q  [(size_t)BATCH*SEQ*DMODEL];     // [b, i, h*64+d]
__device__ float g_k  [(size_t)BATCH*SEQ*DH];         // [b, j, d]
__device__ float g_v  [(size_t)BATCH*SEQ*DH];         // [b, j, d]
__device__ float g_ctx[(size_t)BATCH*SEQ*DMODEL];     // [b, i, h*64+d]

// ===========================================================================
// Fused attention: for each i (CTA handles IT of them), all 64 bh rows:
//   S[bh, j] = q[b,i,h]·k[b,j] + q[b,i,h]·rel[i,j]   (j chunked by 32)
//   P = exp(S/8)  (no max-shift: scores are O(5), exp-safe; math identical)
//   l[bh] += rowsum(P);  O[bh, d] += P·V
// Epilogue: ctx = O / l.  rel is read exactly once across the whole grid.
// ===========================================================================
struct FusedSmem {
    float Qs[IT][64][68];     // [i][bh][d]
    float Ks[4][JC][68];      // [b][j][d]     (reused as O staging in epilogue)
    float Vs[4][JC][68];      // [b][j][d]
    float Rs[IT][JC][68];     // [i][j][d]
    float Ps[IT][64][36];     // [i][bh][j]
    float lsum[IT][64];
};

#define FUSED_SMEM_BYTES ((int)sizeof(FusedSmem))

__global__ void fused_attn_kernel(const float* __restrict__ rel)
{
    extern __shared__ float smem_raw[];
    FusedSmem* sm = reinterpret_cast<FusedSmem*>(smem_raw);

    const int tid  = threadIdx.x;
    const int warp = tid >> 5;
    const int wi   = warp >> 2;          // i_local  (0..1)
    const int wr   = warp & 3;           // row block of 16 == batch b (0..3)
    const int i0   = blockIdx.x * IT;

    if (tid < IT*64) (&sm->lsum[0][0])[tid] = 0.0f;

    // Load Q rows for both i values: [i][bh][d], tf32-rounded
    for (int s = tid; s < IT*64*16; s += 256) {
        int il = s >> 10;
        int r  = (s >> 4) & 63;
        int c4 = (s & 15) * 4;
        int b = r >> 4, h = r & 15;
        float4 v = *reinterpret_cast<const float4*>(
            g_q + ((size_t)(b*SEQ + i0 + il))*DMODEL + h*DH + c4);
        float* dst = &sm->Qs[il][r][c4];
        dst[0] = wmma::__float_to_tf32(v.x);
        dst[1] = wmma::__float_to_tf32(v.y);
        dst[2] = wmma::__float_to_tf32(v.z);
        dst[3] = wmma::__float_to_tf32(v.w);
    }
    __syncthreads();

    // O accumulator: warp owns O[wi][wr*16 .. +16][0..63] -> 4 n-frags
    wmma::fragment<wmma::accumulator, 16, 16, 8, float> of[4];
    #pragma unroll
    for (int nf = 0; nf < 4; ++nf) wmma::fill_fragment(of[nf], 0.0f);

    for (int j0 = 0; j0 < SEQ; j0 += JC) {
        // ---- stage K, V (all 4 batches) and rel (both i) for this j chunk
        for (int s = tid; s < 2048; s += 256) {
            int b  = s >> 9;
            int j  = (s >> 4) & 31;
            int c4 = (s & 15) * 4;
            size_t g = ((size_t)(b*SEQ + j0 + j))*DH + c4;
            float4 kv = *reinterpret_cast<const float4*>(g_k + g);
            float* dk = &sm->Ks[b][j][c4];
            dk[0] = wmma::__float_to_tf32(kv.x);
            dk[1] = wmma::__float_to_tf32(kv.y);
            dk[2] = wmma::__float_to_tf32(kv.z);
            dk[3] = wmma::__float_to_tf32(kv.w);
            float4 vv = *reinterpret_cast<const float4*>(g_v + g);
            float* dv = &sm->Vs[b][j][c4];
            dv[0] = wmma::__float_to_tf32(vv.x);
            dv[1] = wmma::__float_to_tf32(vv.y);
            dv[2] = wmma::__float_to_tf32(vv.z);
            dv[3] = wmma::__float_to_tf32(vv.w);
        }
        for (int s = tid; s < 1024; s += 256) {
            int il = s >> 9;
            int j  = (s >> 4) & 31;
            int c4 = (s & 15) * 4;
            float4 rv = *reinterpret_cast<const float4*>(
                rel + ((size_t)((i0 + il)*SEQ + j0 + j))*DH + c4);
            float* dr = &sm->Rs[il][j][c4];
            dr[0] = wmma::__float_to_tf32(rv.x);
            dr[1] = wmma::__float_to_tf32(rv.y);
            dr[2] = wmma::__float_to_tf32(rv.z);
            dr[3] = wmma::__float_to_tf32(rv.w);
        }
        __syncthreads();

        // ---- S = Q·K_b^T + Q·R_i^T   (warp: 16 rows x 32 j, 2 n-frags)
        wmma::fragment<wmma::accumulator, 16, 16, 8, float> sf[2];
        wmma::fill_fragment(sf[0], 0.0f);
        wmma::fill_fragment(sf[1], 0.0f);
        #pragma unroll
        for (int kf = 0; kf < 8; ++kf) {
            wmma::fragment<wmma::matrix_a, 16, 16, 8, wmma::precision::tf32, wmma::row_major> af;
            wmma::load_matrix_sync(af, &sm->Qs[wi][wr*16][kf*8], 68);
            #pragma unroll
            for (int ni = 0; ni < 2; ++ni) {
                wmma::fragment<wmma::matrix_b, 16, 16, 8, wmma::precision::tf32, wmma::col_major> bk, br;
                wmma::load_matrix_sync(bk, &sm->Ks[wr][ni*16][kf*8], 68);
                wmma::mma_sync(sf[ni], af, bk, sf[ni]);
                wmma::load_matrix_sync(br, &sm->Rs[wi][ni*16][kf*8], 68);
                wmma::mma_sync(sf[ni], af, br, sf[ni]);
            }
        }
        // exp((c2c+c2p)/8) in-register (elementwise: frag mapping irrelevant)
        #pragma unroll
        for (int ni = 0; ni < 2; ++ni) {
            #pragma unroll
            for (int t = 0; t < sf[ni].num_elements; ++t)
                sf[ni].x[t] = wmma::__float_to_tf32(__expf(sf[ni].x[t] * 0.125f));
            wmma::store_matrix_sync(&sm->Ps[wi][wr*16][ni*16], sf[ni], 36,
                                    wmma::mem_row_major);
        }
        __syncthreads();

        // ---- row sums of P (2 threads per row)
        {
            int rg   = tid >> 1;          // 0..127
            int half = tid & 1;
            int il = rg >> 6, r = rg & 63;
            float ssum = 0.0f;
            #pragma unroll
            for (int c = 0; c < 16; ++c) ssum += sm->Ps[il][r][half*16 + c];
            ssum += __shfl_xor_sync(0xffffffffu, ssum, 1);
            if (half == 0) sm->lsum[il][r] += ssum;
        }

        // ---- O += P · V_b   (warp: 16 rows x 64 d)
        #pragma unroll
        for (int kf = 0; kf < 4; ++kf) {
            wmma::fragment<wmma::matrix_a, 16, 16, 8, wmma::precision::tf32, wmma::row_major> af;
            wmma::load_matrix_sync(af, &sm->Ps[wi][wr*16][kf*8], 36);
            #pragma unroll
            for (int nf = 0; nf < 4; ++nf) {
                wmma::fragment<wmma::matrix_b, 16, 16, 8, wmma::precision::tf32, wmma::row_major> bf;
                wmma::load_matrix_sync(bf, &sm->Vs[wr][kf*8][nf*16], 68);
                wmma::mma_sync(of[nf], af, bf, of[nf]);
            }
        }
        __syncthreads();
    }

    // ---- epilogue: stage O (reuse Ks memory: 2*64*68 == 4*32*68 floats)
    float (*stage)[64][68] = reinterpret_cast<float (*)[64][68]>(&sm->Ks[0][0][0]);
    #pragma unroll
    for (int nf = 0; nf < 4; ++nf)
        wmma::store_matrix_sync(&stage[wi][wr*16][nf*16], of[nf], 68,
                                wmma::mem_row_major);
    __syncthreads();

    for (int s = tid; s < IT*64*16; s += 256) {
        int il = s >> 10;
        int r  = (s >> 4) & 63;
        int c4 = (s & 15) * 4;
        float inv = 1.0f / sm->lsum[il][r];
        float4 o;
        o.x = stage[il][r][c4+0] * inv;
        o.y = stage[il][r][c4+1] * inv;
        o.z = stage[il][r][c4+2] * inv;
        o.w = stage[il][r][c4+3] * inv;
        int b = r >> 4, h = r & 15;
        *reinterpret_cast<float4*>(
            g_ctx + ((size_t)(b*SEQ + i0 + il))*DMODEL + h*DH + c4) = o;
    }
}

// ===========================================================================
// 128x128-tile NT GEMM (C = A·B^T), 8 warps, warp = 32x64.  For Q/O proj.
// ===========================================================================
__global__ void gemm_nt_128(const float* __restrict__ A, int lda,
                            const float* __restrict__ B, int ldb,
                            float* __restrict__ C, int ldc, int K)
{
    __shared__ float As[128][36];
    __shared__ float Bs[128][36];
    const int tid  = threadIdx.x;
    const int warp = tid >> 5;
    const int wm   = warp >> 1;     // 0..3 (32-row block)
    const int wn   = warp & 1;      // 0..1 (64-col block)

    A += (size_t)blockIdx.x * 128 * lda;
    B += (size_t)blockIdx.y * 128 * ldb;
    C += (size_t)blockIdx.x * 128 * ldc + (size_t)blockIdx.y * 128;

    wmma::fragment<wmma::accumulator, 16, 16, 8, float> cf[2][4];
    #pragma unroll
    for (int mi = 0; mi < 2; ++mi)
        #pragma unroll
        for (int ni = 0; ni < 4; ++ni)
            wmma::fill_fragment(cf[mi][ni], 0.0f);

    for (int k0 = 0; k0 < K; k0 += 32) {
        #pragma unroll
        for (int it = 0; it < 4; ++it) {
            int s = tid + it*256;
            int r = s >> 3;
            int c = (s & 7) * 4;
            float4 va = *reinterpret_cast<const float4*>(A + (size_t)r*lda + k0 + c);
            As[r][c+0] = wmma::__float_to_tf32(va.x);
            As[r][c+1] = wmma::__float_to_tf32(va.y);
            As[r][c+2] = wmma::__float_to_tf32(va.z);
            As[r][c+3] = wmma::__float_to_tf32(va.w);
            float4 vb = *reinterpret_cast<const float4*>(B + (size_t)r*ldb + k0 + c);
            Bs[r][c+0] = wmma::__float_to_tf32(vb.x);
            Bs[r][c+1] = wmma::__float_to_tf32(vb.y);
            Bs[r][c+2] = wmma::__float_to_tf32(vb.z);
            Bs[r][c+3] = wmma::__float_to_tf32(vb.w);
        }
        __syncthreads();

        #pragma unroll
        for (int kf = 0; kf < 4; ++kf) {
            wmma::fragment<wmma::matrix_a, 16, 16, 8, wmma::precision::tf32, wmma::row_major> af[2];
            wmma::fragment<wmma::matrix_b, 16, 16, 8, wmma::precision::tf32, wmma::col_major> bf[4];
            #pragma unroll
            for (int mi = 0; mi < 2; ++mi)
                wmma::load_matrix_sync(af[mi], &As[wm*32 + mi*16][kf*8], 36);
            #pragma unroll
            for (int ni = 0; ni < 4; ++ni)
                wmma::load_matrix_sync(bf[ni], &Bs[wn*64 + ni*16][kf*8], 36);
            #pragma unroll
            for (int mi = 0; mi < 2; ++mi)
                #pragma unroll
                for (int ni = 0; ni < 4; ++ni)
                    wmma::mma_sync(cf[mi][ni], af[mi], bf[ni], cf[mi][ni]);
        }
        __syncthreads();
    }

    #pragma unroll
    for (int mi = 0; mi < 2; ++mi)
        #pragma unroll
        for (int ni = 0; ni < 4; ++ni)
            wmma::store_matrix_sync(
                C + (size_t)(wm*32 + mi*16)*ldc + (wn*64 + ni*16),
                cf[mi][ni], ldc, wmma::mem_row_major);
}

// ===========================================================================
// 64x64-tile NT GEMM (for the narrow K/V projections, N = 64)
// ===========================================================================
__global__ void gemm_nt_64k(const float* __restrict__ A, int lda,
                            const float* __restrict__ B, int ldb,
                            float* __restrict__ C, int ldc, int K)
{
    __shared__ float As[64][36];
    __shared__ float Bs[64][36];
    const int tid  = threadIdx.x;
    const int warp = tid >> 5;
    const int wm   = warp >> 1;
    const int wn   = warp & 1;

    A += (size_t)blockIdx.x * 64 * lda;
    C += (size_t)blockIdx.x * 64 * ldc;

    wmma::fragment<wmma::accumulator, 16, 16, 8, float> cf[2][2];
    #pragma unroll
    for (int mi = 0; mi < 2; ++mi)
        #pragma unroll
        for (int ni = 0; ni < 2; ++ni)
            wmma::fill_fragment(cf[mi][ni], 0.0f);

    for (int k0 = 0; k0 < K; k0 += 32) {
        #pragma unroll
        for (int it = 0; it < 4; ++it) {
            int s = tid + it*128;
            int r = s >> 3;
            int c = (s & 7) * 4;
            float4 va = *reinterpret_cast<const float4*>(A + (size_t)r*lda + k0 + c);
            As[r][c+0] = wmma::__float_to_tf32(va.x);
            As[r][c+1] = wmma::__float_to_tf32(va.y);
            As[r][c+2] = wmma::__float_to_tf32(va.z);
            As[r][c+3] = wmma::__float_to_tf32(va.w);
            float4 vb = *reinterpret_cast<const float4*>(B + (size_t)r*ldb + k0 + c);
            Bs[r][c+0] = wmma::__float_to_tf32(vb.x);
            Bs[r][c+1] = wmma::__float_to_tf32(vb.y);
            Bs[r][c+2] = wmma::__float_to_tf32(vb.z);
            Bs[r][c+3] = wmma::__float_to_tf32(vb.w);
        }
        __syncthreads();

        #pragma unroll
        for (int kf = 0; kf < 4; ++kf) {
            wmma::fragment<wmma::matrix_a, 16, 16, 8, wmma::precision::tf32, wmma::row_major> af[2];
            wmma::fragment<wmma::matrix_b, 16, 16, 8, wmma::precision::tf32, wmma::col_major> bf[2];
            #pragma unroll
            for (int mi = 0; mi < 2; ++mi)
                wmma::load_matrix_sync(af[mi], &As[wm*32 + mi*16][kf*8], 36);
            #pragma unroll
            for (int ni = 0; ni < 2; ++ni)
                wmma::load_matrix_sync(bf[ni], &Bs[wn*32 + ni*16][kf*8], 36);
            #pragma unroll
            for (int mi = 0; mi < 2; ++mi)
                #pragma unroll
                for (int ni = 0; ni < 2; ++ni)
                    wmma::mma_sync(cf[mi][ni], af[mi], bf[ni], cf[mi][ni]);
        }
        __syncthreads();
    }

    #pragma unroll
    for (int mi = 0; mi < 2; ++mi)
        #pragma unroll
        for (int ni = 0; ni < 2; ++ni)
            wmma::store_matrix_sync(
                C + (size_t)(wm*32 + mi*16)*ldc + (wn*32 + ni*16),
                cf[mi][ni], ldc, wmma::mem_row_major);
}

// ---------------------------------------------------------------------------
__global__ void bias_add(float* __restrict__ out, const float* __restrict__ bo)
{
    size_t idx = (size_t)blockIdx.x * 256 + threadIdx.x;
    out[idx] += bo[idx & (DMODEL - 1)];
}

// ---------------------------------------------------------------------------
extern "C" void kernel_launch(void* const* d_in, const int* in_sizes, int n_in,
                              void* d_out, int out_size)
{
    const float* x   = (const float*)d_in[0];
    const float* rel = (const float*)d_in[1];
    const float* Wq  = (const float*)d_in[2];
    const float* Wk  = (const float*)d_in[3];
    const float* Wv  = (const float*)d_in[4];
    const float* Wo  = (const float*)d_in[5];
    const float* bo  = (const float*)d_in[6];
    float* out = (float*)d_out;

    float *q, *k, *v, *ctx;
    cudaGetSymbolAddress((void**)&q,   g_q);
    cudaGetSymbolAddress((void**)&k,   g_k);
    cudaGetSymbolAddress((void**)&v,   g_v);
    cudaGetSymbolAddress((void**)&ctx, g_ctx);

    cudaFuncSetAttribute(fused_attn_kernel,
                         cudaFuncAttributeMaxDynamicSharedMemorySize,
                         FUSED_SMEM_BYTES);

    // Projections: y = x @ W^T
    gemm_nt_128<<<dim3(32, 8), 256>>>(x, DMODEL, Wq, DMODEL, q, DMODEL, DMODEL);
    gemm_nt_64k<<<dim3(64, 1), 128>>>(x, DMODEL, Wk, DMODEL, k, DH, DMODEL);
    gemm_nt_64k<<<dim3(64, 1), 128>>>(x, DMODEL, Wv, DMODEL, v, DH, DMODEL);

    // Fused c2c + c2p + softmax + AV (scores never hit HBM)
    fused_attn_kernel<<<SEQ/IT, 256, FUSED_SMEM_BYTES>>>(rel);

    // out = ctx @ Wo^T + bo
    gemm_nt_128<<<dim3(32, 8), 256>>>(ctx, DMODEL, Wo, DMODEL, out, DMODEL, DMODEL);
    bias_add<<<16384, 256>>>(out, bo);
}

// round 8
// speedup vs baseline: 1.5182x; 1.5182x over previous
#include <cuda_runtime.h>
#include <cstdint>
#include <mma.h>

using namespace nvcuda;

#define DMODEL 1024
#define NH     16
#define DH     64
#define BATCH  4
#define SEQ    1024
#define JC2    64

// Scratch (static device globals)
__device__ float g_q  [(size_t)BATCH*SEQ*DMODEL];   // [b, i, h*64+d]
__device__ float g_k  [(size_t)BATCH*SEQ*DH];       // [b, j, d]
__device__ float g_v  [(size_t)BATCH*SEQ*DH];       // [b, j, d]
__device__ float g_p  [(size_t)64*SEQ*SEQ];         // [b][i][h][j]  (268 MB)
__device__ float g_l  [(size_t)BATCH*SEQ*NH];       // row sums, index (b*SEQ+i)*16+h
__device__ float g_ctx[(size_t)BATCH*SEQ*DMODEL];   // [b, i, h*64+d]

// ---------------------------------------------------------------------------
__device__ __forceinline__ void cp16(void* dst, const void* src) {
    unsigned d = (unsigned)__cvta_generic_to_shared(dst);
    asm volatile("cp.async.cg.shared.global [%0], [%1], 16;" :: "r"(d), "l"(src));
}
__device__ __forceinline__ void cp_commit() { asm volatile("cp.async.commit_group;"); }
template<int N> __device__ __forceinline__ void cp_wait() {
    asm volatile("cp.async.wait_group %0;" :: "n"(N));
}
template<class F> __device__ __forceinline__ void to_tf32(F& f) {
    #pragma unroll
    for (int t = 0; t < f.num_elements; ++t)
        f.x[t] = wmma::__float_to_tf32(f.x[t]);
}

// ===========================================================================
// 128x128 NT GEMM (C = A·B^T), cp.async double-buffered, 8 warps (warp 32x64)
// ===========================================================================
struct ProjSmem { float A[2][128][36]; float B[2][128][36]; };
#define PROJ_SMEM ((int)sizeof(ProjSmem))

__global__ void __launch_bounds__(256, 2)
gemm_nt_128p(const float* __restrict__ A, int lda,
             const float* __restrict__ B, int ldb,
             float* __restrict__ C, int ldc, int K)
{
    extern __shared__ float smraw[];
    ProjSmem* sm = reinterpret_cast<ProjSmem*>(smraw);

    const int tid  = threadIdx.x;
    const int warp = tid >> 5;
    const int wm   = warp >> 1;      // 0..3
    const int wn   = warp & 1;       // 0..1

    A += (size_t)blockIdx.x * 128 * lda;
    B += (size_t)blockIdx.y * 128 * ldb;
    C += (size_t)blockIdx.x * 128 * ldc + (size_t)blockIdx.y * 128;

    auto stage = [&](int buf, int k0) {
        #pragma unroll
        for (int t = 0; t < 4; ++t) {
            int idx = tid + t*256;           // 0..1023
            int r   = idx >> 3;              // 0..127
            int c4  = (idx & 7) * 4;         // 0..28
            cp16(&sm->A[buf][r][c4], A + (size_t)r*lda + k0 + c4);
            cp16(&sm->B[buf][r][c4], B + (size_t)r*ldb + k0 + c4);
        }
        cp_commit();
    };

    wmma::fragment<wmma::accumulator, 16, 16, 8, float> cf[2][4];
    #pragma unroll
    for (int mi = 0; mi < 2; ++mi)
        #pragma unroll
        for (int ni = 0; ni < 4; ++ni) wmma::fill_fragment(cf[mi][ni], 0.0f);

    stage(0, 0);
    int cur = 0;
    for (int k0 = 0; k0 < K; k0 += 32) {
        if (k0 + 32 < K) { stage(cur ^ 1, k0 + 32); cp_wait<1>(); }
        else             { cp_wait<0>(); }
        __syncthreads();

        #pragma unroll
        for (int kf = 0; kf < 4; ++kf) {
            wmma::fragment<wmma::matrix_a, 16, 16, 8, wmma::precision::tf32, wmma::row_major> af[2];
            wmma::fragment<wmma::matrix_b, 16, 16, 8, wmma::precision::tf32, wmma::col_major> bf[4];
            #pragma unroll
            for (int mi = 0; mi < 2; ++mi) {
                wmma::load_matrix_sync(af[mi], &sm->A[cur][wm*32 + mi*16][kf*8], 36);
                to_tf32(af[mi]);
            }
            #pragma unroll
            for (int ni = 0; ni < 4; ++ni) {
                wmma::load_matrix_sync(bf[ni], &sm->B[cur][wn*64 + ni*16][kf*8], 36);
                to_tf32(bf[ni]);
            }
            #pragma unroll
            for (int mi = 0; mi < 2; ++mi)
                #pragma unroll
                for (int ni = 0; ni < 4; ++ni)
                    wmma::mma_sync(cf[mi][ni], af[mi], bf[ni], cf[mi][ni]);
        }
        __syncthreads();
        cur ^= 1;
    }

    #pragma unroll
    for (int mi = 0; mi < 2; ++mi)
        #pragma unroll
        for (int ni = 0; ni < 4; ++ni)
            wmma::store_matrix_sync(
                C + (size_t)(wm*32 + mi*16)*ldc + (wn*64 + ni*16),
                cf[mi][ni], ldc, wmma::mem_row_major);
}

// ===========================================================================
// 64x64-tile NT GEMM for the narrow K/V projections (N = 64)
// ===========================================================================
__global__ void gemm_nt_64k(const float* __restrict__ A, int lda,
                            const float* __restrict__ B, int ldb,
                            float* __restrict__ C, int ldc, int K)
{
    __shared__ float As[64][36];
    __shared__ float Bs[64][36];
    const int tid  = threadIdx.x;
    const int warp = tid >> 5;
    const int wm   = warp >> 1;
    const int wn   = warp & 1;

    A += (size_t)blockIdx.x * 64 * lda;
    C += (size_t)blockIdx.x * 64 * ldc;

    wmma::fragment<wmma::accumulator, 16, 16, 8, float> cf[2][2];
    #pragma unroll
    for (int mi = 0; mi < 2; ++mi)
        #pragma unroll
        for (int ni = 0; ni < 2; ++ni) wmma::fill_fragment(cf[mi][ni], 0.0f);

    for (int k0 = 0; k0 < K; k0 += 32) {
        #pragma unroll
        for (int it = 0; it < 4; ++it) {
            int s = tid + it*128;
            int r = s >> 3;
            int c = (s & 7) * 4;
            float4 va = *reinterpret_cast<const float4*>(A + (size_t)r*lda + k0 + c);
            As[r][c+0] = wmma::__float_to_tf32(va.x);
            As[r][c+1] = wmma::__float_to_tf32(va.y);
            As[r][c+2] = wmma::__float_to_tf32(va.z);
            As[r][c+3] = wmma::__float_to_tf32(va.w);
            float4 vb = *reinterpret_cast<const float4*>(B + (size_t)r*ldb + k0 + c);
            Bs[r][c+0] = wmma::__float_to_tf32(vb.x);
            Bs[r][c+1] = wmma::__float_to_tf32(vb.y);
            Bs[r][c+2] = wmma::__float_to_tf32(vb.z);
            Bs[r][c+3] = wmma::__float_to_tf32(vb.w);
        }
        __syncthreads();

        #pragma unroll
        for (int kf = 0; kf < 4; ++kf) {
            wmma::fragment<wmma::matrix_a, 16, 16, 8, wmma::precision::tf32, wmma::row_major> af[2];
            wmma::fragment<wmma::matrix_b, 16, 16, 8, wmma::precision::tf32, wmma::col_major> bf[2];
            #pragma unroll
            for (int mi = 0; mi < 2; ++mi)
                wmma::load_matrix_sync(af[mi], &As[wm*32 + mi*16][kf*8], 36);
            #pragma unroll
            for (int ni = 0; ni < 2; ++ni)
                wmma::load_matrix_sync(bf[ni], &Bs[wn*32 + ni*16][kf*8], 36);
            #pragma unroll
            for (int mi = 0; mi < 2; ++mi)
                #pragma unroll
                for (int ni = 0; ni < 2; ++ni)
                    wmma::mma_sync(cf[mi][ni], af[mi], bf[ni], cf[mi][ni]);
        }
        __syncthreads();
    }

    #pragma unroll
    for (int mi = 0; mi < 2; ++mi)
        #pragma unroll
        for (int ni = 0; ni < 2; ++ni)
            wmma::store_matrix_sync(
                C + (size_t)(wm*32 + mi*16)*ldc + (wn*32 + ni*16),
                cf[mi][ni], ldc, wmma::mem_row_major);
}

// ===========================================================================
// c2cp: P[b,i,h,j] = exp((q·k + q·rel)/8), plus row-sum atomics into g_l.
// One-shot CTA per (i, j-tile of 64). 8 warps: (b = warp>>1) x (j-half = warp&1).
// ===========================================================================
struct C2PSmem {
    float Qs[64][68];        // rows (b,h), cols d
    float Ks[4][JC2][68];    // [b][j][d]
    float Rs[JC2][68];       // [j][d]; reused as P staging [64][68]
};
#define C2P_SMEM ((int)sizeof(C2PSmem))

__global__ void __launch_bounds__(256, 2)
c2cp_kernel(const float* __restrict__ rel)
{
    extern __shared__ float smraw[];
    C2PSmem* sm = reinterpret_cast<C2PSmem*>(smraw);

    const int tid  = threadIdx.x;
    const int warp = tid >> 5;
    const int wb   = warp >> 1;        // batch 0..3
    const int wn   = warp & 1;         // j half
    const int i    = blockIdx.x;
    const int j0   = blockIdx.y * JC2;

    // Stage Q (gathered rows) and rel
    #pragma unroll
    for (int t = 0; t < 4; ++t) {
        int idx = tid + t*256;          // 0..1023
        int r   = idx >> 4;             // 0..63
        int c4  = (idx & 15) * 4;
        int b = r >> 4, h = r & 15;
        cp16(&sm->Qs[r][c4], g_q + ((size_t)(b*SEQ + i))*DMODEL + h*DH + c4);
        cp16(&sm->Rs[r][c4], rel + ((size_t)i*SEQ + j0 + r)*DH + c4);
    }
    // Stage K (all 4 batches)
    #pragma unroll
    for (int t = 0; t < 16; ++t) {
        int idx = tid + t*256;          // 0..4095
        int b   = idx >> 10;
        int r   = (idx >> 4) & 63;
        int c4  = (idx & 15) * 4;
        cp16(&sm->Ks[b][r][c4], g_k + ((size_t)(b*SEQ + j0 + r))*DH + c4);
    }
    cp_commit();
    cp_wait<0>();
    __syncthreads();

    // S = Q·K_b^T + Q·R^T   (warp: 16 h-rows x 32 j)
    wmma::fragment<wmma::accumulator, 16, 16, 8, float> sf[2];
    wmma::fill_fragment(sf[0], 0.0f);
    wmma::fill_fragment(sf[1], 0.0f);
    #pragma unroll
    for (int kf = 0; kf < 8; ++kf) {
        wmma::fragment<wmma::matrix_a, 16, 16, 8, wmma::precision::tf32, wmma::row_major> af;
        wmma::load_matrix_sync(af, &sm->Qs[wb*16][kf*8], 68);
        to_tf32(af);
        #pragma unroll
        for (int ni = 0; ni < 2; ++ni) {
            wmma::fragment<wmma::matrix_b, 16, 16, 8, wmma::precision::tf32, wmma::col_major> bk, br;
            wmma::load_matrix_sync(bk, &sm->Ks[wb][wn*32 + ni*16][kf*8], 68);
            to_tf32(bk);
            wmma::mma_sync(sf[ni], af, bk, sf[ni]);
            wmma::load_matrix_sync(br, &sm->Rs[wn*32 + ni*16][kf*8], 68);
            to_tf32(br);
            wmma::mma_sync(sf[ni], af, br, sf[ni]);
        }
    }
    // exp((c2c+c2p)/8) elementwise in-register
    #pragma unroll
    for (int ni = 0; ni < 2; ++ni)
        #pragma unroll
        for (int t = 0; t < sf[ni].num_elements; ++t)
            sf[ni].x[t] = __expf(sf[ni].x[t] * 0.125f);

    __syncthreads();   // all warps done reading Rs; safe to reuse as P staging
    float (*Ps)[68] = reinterpret_cast<float (*)[68]>(&sm->Rs[0][0]);
    #pragma unroll
    for (int ni = 0; ni < 2; ++ni)
        wmma::store_matrix_sync(&Ps[wb*16][wn*32 + ni*16], sf[ni], 68,
                                wmma::mem_row_major);
    __syncthreads();

    // Writeout + row-sum atomics: 4 threads per row
    {
        int r = tid >> 2;           // 0..63   (b,h)
        int q = tid & 3;            // 16-col quarter
        int b = r >> 4, h = r & 15;
        size_t grow = ((size_t)(b*SEQ + i))*16 + h;
        float* dst = g_p + grow*SEQ + j0 + q*16;
        float s = 0.0f;
        #pragma unroll
        for (int c = 0; c < 4; ++c) {
            float4 v = *reinterpret_cast<float4*>(&Ps[r][q*16 + c*4]);
            s += v.x + v.y + v.z + v.w;
            *reinterpret_cast<float4*>(dst + c*4) = v;
        }
        s += __shfl_xor_sync(0xffffffffu, s, 1);
        s += __shfl_xor_sync(0xffffffffu, s, 2);
        if (q == 0) atomicAdd(&g_l[grow], s);
    }
}

// ===========================================================================
// AV: ctx[b,(i,h),d] = (P_b[(i,h),:] · V_b) / l.  Per-b GEMM M=16384,N=64,K=1024
// cp.async double-buffered. grid (128 m-tiles, b)
// ===========================================================================
struct AvSmem { float A[2][128][36]; float B[2][32][68]; };
#define AV_SMEM ((int)sizeof(AvSmem))

__global__ void __launch_bounds__(256, 2)
av_kernel()
{
    extern __shared__ float smraw[];
    AvSmem* sm = reinterpret_cast<AvSmem*>(smraw);

    const int tid  = threadIdx.x;
    const int warp = tid >> 5;
    const int wm   = warp >> 1;        // 0..3
    const int wn   = warp & 1;         // 0..1
    const int b    = blockIdx.y;
    const size_t m0 = (size_t)blockIdx.x * 128;

    const float* Pb = g_p + (size_t)b*SEQ*16*SEQ + m0*SEQ;
    const float* Vb = g_v + (size_t)b*SEQ*DH;
    float*       Cb = g_ctx + ((size_t)b*SEQ*16 + m0)*DH;

    auto stage = [&](int buf, int k0) {
        #pragma unroll
        for (int t = 0; t < 4; ++t) {
            int idx = tid + t*256;          // 0..1023
            int r   = idx >> 3;             // 0..127
            int c4  = (idx & 7) * 4;
            cp16(&sm->A[buf][r][c4], Pb + (size_t)r*SEQ + k0 + c4);
        }
        #pragma unroll
        for (int t = 0; t < 2; ++t) {
            int idx = tid + t*256;          // 0..511
            int r   = idx >> 4;             // 0..31
            int c4  = (idx & 15) * 4;
            cp16(&sm->B[buf][r][c4], Vb + (size_t)(k0 + r)*DH + c4);
        }
        cp_commit();
    };

    wmma::fragment<wmma::accumulator, 16, 16, 8, float> of[2][2];
    #pragma unroll
    for (int mi = 0; mi < 2; ++mi)
        #pragma unroll
        for (int ni = 0; ni < 2; ++ni) wmma::fill_fragment(of[mi][ni], 0.0f);

    stage(0, 0);
    int cur = 0;
    for (int k0 = 0; k0 < SEQ; k0 += 32) {
        if (k0 + 32 < SEQ) { stage(cur ^ 1, k0 + 32); cp_wait<1>(); }
        else               { cp_wait<0>(); }
        __syncthreads();

        #pragma unroll
        for (int kf = 0; kf < 4; ++kf) {
            wmma::fragment<wmma::matrix_a, 16, 16, 8, wmma::precision::tf32, wmma::row_major> af[2];
            wmma::fragment<wmma::matrix_b, 16, 16, 8, wmma::precision::tf32, wmma::row_major> bf[2];
            #pragma unroll
            for (int mi = 0; mi < 2; ++mi) {
                wmma::load_matrix_sync(af[mi], &sm->A[cur][wm*32 + mi*16][kf*8], 36);
                to_tf32(af[mi]);
            }
            #pragma unroll
            for (int ni = 0; ni < 2; ++ni) {
                wmma::load_matrix_sync(bf[ni], &sm->B[cur][kf*8][wn*32 + ni*16], 68);
                to_tf32(bf[ni]);
            }
            #pragma unroll
            for (int mi = 0; mi < 2; ++mi)
                #pragma unroll
                for (int ni = 0; ni < 2; ++ni)
                    wmma::mma_sync(of[mi][ni], af[mi], bf[ni], of[mi][ni]);
        }
        __syncthreads();
        cur ^= 1;
    }

    // Epilogue: stage O through smem (alias over A buffers), divide by l
    float (*Cs)[68] = reinterpret_cast<float (*)[68]>(&sm->A[0][0][0]);
    #pragma unroll
    for (int mi = 0; mi < 2; ++mi)
        #pragma unroll
        for (int ni = 0; ni < 2; ++ni)
            wmma::store_matrix_sync(&Cs[wm*32 + mi*16][wn*32 + ni*16],
                                    of[mi][ni], 68, wmma::mem_row_major);
    __syncthreads();

    {
        int r    = tid >> 1;       // 0..127
        int half = tid & 1;
        float inv = 1.0f / g_l[(size_t)b*SEQ*16 + m0 + r];
        #pragma unroll
        for (int c = 0; c < 8; ++c) {
            float4 v = *reinterpret_cast<float4*>(&Cs[r][half*32 + c*4]);
            v.x *= inv; v.y *= inv; v.z *= inv; v.w *= inv;
            *reinterpret_cast<float4*>(Cb + (size_t)r*DH + half*32 + c*4) = v;
        }
    }
}

// ---------------------------------------------------------------------------
__global__ void bias_add(float* __restrict__ out, const float* __restrict__ bo)
{
    size_t idx = (size_t)blockIdx.x * 256 + threadIdx.x;
    out[idx] += bo[idx & (DMODEL - 1)];
}

// ---------------------------------------------------------------------------
extern "C" void kernel_launch(void* const* d_in, const int* in_sizes, int n_in,
                              void* d_out, int out_size)
{
    const float* x   = (const float*)d_in[0];
    const float* rel = (const float*)d_in[1];
    const float* Wq  = (const float*)d_in[2];
    const float* Wk  = (const float*)d_in[3];
    const float* Wv  = (const float*)d_in[4];
    const float* Wo  = (const float*)d_in[5];
    const float* bo  = (const float*)d_in[6];
    float* out = (float*)d_out;

    float *q, *k, *v, *l, *ctx;
    cudaGetSymbolAddress((void**)&q,   g_q);
    cudaGetSymbolAddress((void**)&k,   g_k);
    cudaGetSymbolAddress((void**)&v,   g_v);
    cudaGetSymbolAddress((void**)&l,   g_l);
    cudaGetSymbolAddress((void**)&ctx, g_ctx);

    cudaFuncSetAttribute(gemm_nt_128p, cudaFuncAttributeMaxDynamicSharedMemorySize, PROJ_SMEM);
    cudaFuncSetAttribute(c2cp_kernel,  cudaFuncAttributeMaxDynamicSharedMemorySize, C2P_SMEM);
    cudaFuncSetAttribute(av_kernel,    cudaFuncAttributeMaxDynamicSharedMemorySize, AV_SMEM);

    // Projections: y = x @ W^T
    gemm_nt_128p<<<dim3(32, 8), 256, PROJ_SMEM>>>(x, DMODEL, Wq, DMODEL, q, DMODEL, DMODEL);
    gemm_nt_64k<<<dim3(64, 1), 128>>>(x, DMODEL, Wk, DMODEL, k, DH, DMODEL);
    gemm_nt_64k<<<dim3(64, 1), 128>>>(x, DMODEL, Wv, DMODEL, v, DH, DMODEL);

    // Zero row-sum accumulators
    cudaMemsetAsync(l, 0, (size_t)BATCH*SEQ*NH*sizeof(float));

    // P = exp((c2c + c2p)/8), row sums via atomics
    c2cp_kernel<<<dim3(SEQ, SEQ/JC2), 256, C2P_SMEM>>>(rel);

    // ctx = (P · V) / l
    av_kernel<<<dim3(128, BATCH), 256, AV_SMEM>>>();

    // out = ctx @ Wo^T + bo
    gemm_nt_128p<<<dim3(32, 8), 256, PROJ_SMEM>>>(ctx, DMODEL, Wo, DMODEL, out, DMODEL, DMODEL);
    bias_add<<<16384, 256>>>(out, bo);
}